// round 1
// baseline (speedup 1.0000x reference)
#include <cuda_runtime.h>
#include <cstdint>

// Kendall's tau loss:
//   loss = 1 - 2 * sum_{i<j} sign(p_i-p_j)*sign(t_i-t_j) / (n(n-1))
// With (effectively) no ties among i<j:
//   sum_{i<j} s_ij = P - 2*D,  P = n(n-1)/2,  D = # discordant pairs
//   => loss = 4*D / (n(n-1))
// Discordant test per pair: XOR of IEEE sign bits of (p_i-p_j) and (t_i-t_j).

#define TILE 256

__device__ unsigned long long g_neg_count;

__global__ void kt_init_kernel() {
    g_neg_count = 0ULL;
}

__global__ __launch_bounds__(TILE) void kt_count_kernel(
    const float* __restrict__ p, const float* __restrict__ t, int n)
{
    const int bi = blockIdx.y;
    const int bj = blockIdx.x;
    if (bj < bi) return;  // upper triangle of tiles only

    __shared__ float sp[TILE];
    __shared__ float st[TILE];

    const int tid = threadIdx.x;

    const int jbase = bj * TILE;
    const int jlim  = min(TILE, n - jbase);   // valid j's in this tile
    if (tid < jlim) {
        sp[tid] = p[jbase + tid];
        st[tid] = t[jbase + tid];
    }
    __syncthreads();

    const int i = bi * TILE + tid;
    unsigned int cnt = 0;

    if (i < n) {
        const float pi = p[i];
        const float ti = t[i];

        if (bi == bj) {
            // diagonal tile: j > i within tile
            for (int j = tid + 1; j < jlim; ++j) {
                float dp = pi - sp[j];
                float dt = ti - st[j];
                cnt += (__float_as_uint(dp) ^ __float_as_uint(dt)) >> 31;
            }
        } else {
            // full tile: every (i, j) has i < j since tile blocks are ordered
            #pragma unroll 8
            for (int j = 0; j < jlim; ++j) {
                float dp = pi - sp[j];
                float dt = ti - st[j];
                cnt += (__float_as_uint(dp) ^ __float_as_uint(dt)) >> 31;
            }
        }
    }

    // intra-block reduction: warp shuffle, then one atomic per block
    #pragma unroll
    for (int off = 16; off > 0; off >>= 1)
        cnt += __shfl_down_sync(0xFFFFFFFFu, cnt, off);

    __shared__ unsigned int wsum[TILE / 32];
    const int lane = tid & 31;
    const int wid  = tid >> 5;
    if (lane == 0) wsum[wid] = cnt;
    __syncthreads();

    if (tid == 0) {
        unsigned int total = 0;
        #pragma unroll
        for (int w = 0; w < TILE / 32; ++w) total += wsum[w];
        if (total) atomicAdd(&g_neg_count, (unsigned long long)total);
    }
}

__global__ void kt_finalize_kernel(float* __restrict__ out, int n)
{
    double nn = (double)n;
    double loss = 4.0 * (double)g_neg_count / (nn * (nn - 1.0));
    out[0] = (float)loss;
}

extern "C" void kernel_launch(void* const* d_in, const int* in_sizes, int n_in,
                              void* d_out, int out_size)
{
    const float* predictions = (const float*)d_in[0];
    const float* true_labels = (const float*)d_in[1];
    float* out = (float*)d_out;
    const int n = in_sizes[0];

    const int ntiles = (n + TILE - 1) / TILE;

    kt_init_kernel<<<1, 1>>>();

    dim3 grid(ntiles, ntiles);
    kt_count_kernel<<<grid, TILE>>>(predictions, true_labels, n);

    kt_finalize_kernel<<<1, 1>>>(out, n);
}

// round 2
// speedup vs baseline: 1.2799x; 1.2799x over previous
#include <cuda_runtime.h>
#include <cstdint>

// Kendall's tau loss via discordant-pair count (no ties in random normals):
//   loss = 4*D / (n(n-1)),  D = #{i<j : sign(p_i-p_j) != sign(t_i-t_j)}
// Per pair: one packed f32x2 add computes both diffs; discord = XOR of the
// two halves' IEEE sign bits. Single kernel: last block finalizes + resets.

#define TILE 512
#define NTHREADS 256

__device__ unsigned long long g_cnt = 0;
__device__ unsigned int g_done = 0;

__device__ __forceinline__ unsigned long long pack2(float lo, float hi) {
    unsigned long long r;
    asm("mov.b64 %0, {%1, %2};" : "=l"(r) : "f"(lo), "f"(hi));
    return r;
}

// a = (p_i, t_i), nb = (-p_j, -t_j). Returns 1 if signs of (p_i-p_j) and
// (t_i-t_j) differ, else 0.  FADD2 + LOP3 + LEA.HI expected.
__device__ __forceinline__ unsigned int sign_discord(unsigned long long a,
                                                     unsigned long long nb) {
    unsigned long long s;
    asm("add.rn.f32x2 %0, %1, %2;" : "=l"(s) : "l"(a), "l"(nb));
    unsigned int lo, hi;
    asm("mov.b64 {%0, %1}, %2;" : "=r"(lo), "=r"(hi) : "l"(s));
    return (lo ^ hi) >> 31;
}

__global__ __launch_bounds__(NTHREADS) void kt_kernel(
    const float* __restrict__ p, const float* __restrict__ t,
    float* __restrict__ out, int n)
{
    const int ntiles = (n + TILE - 1) / TILE;

    // Decode linear block id -> upper-triangular (bi, bj), bj >= bi.
    int b = blockIdx.x;
    int bi = 0;
    while (b >= ntiles - bi) { b -= ntiles - bi; ++bi; }
    const int bj = bi + b;

    __shared__ float2 snb[TILE];  // (-p_j, -t_j) for this j-tile

    const int tid = threadIdx.x;
    const int jb = bj * TILE;
    const int jlim = min(TILE, n - jb);

    #pragma unroll
    for (int k = tid; k < TILE; k += NTHREADS) {
        if (k < jlim) {
            snb[k] = make_float2(-p[jb + k], -t[jb + k]);
        }
    }
    __syncthreads();

    const unsigned long long* B =
        reinterpret_cast<const unsigned long long*>(snb);

    const int i0 = bi * TILE + tid;
    const int i1 = i0 + NTHREADS;
    unsigned int cnt = 0;

    const bool full = (jlim == TILE) && (bi * TILE + TILE <= n);

    if (full && bi != bj) {
        // Full off-diagonal tile: every (i, j) has i < j.
        const unsigned long long a0 = pack2(p[i0], t[i0]);
        const unsigned long long a1 = pack2(p[i1], t[i1]);
        #pragma unroll 8
        for (int k = 0; k < TILE; ++k) {
            const unsigned long long bk = B[k];
            cnt += sign_discord(a0, bk);
            cnt += sign_discord(a1, bk);
        }
    } else if (full) {
        // Full diagonal tile: j > i locally.
        const unsigned long long a0 = pack2(p[i0], t[i0]);
        const unsigned long long a1 = pack2(p[i1], t[i1]);
        #pragma unroll 8
        for (int k = tid + 1; k < TILE; ++k)
            cnt += sign_discord(a0, B[k]);
        #pragma unroll 8
        for (int k = tid + NTHREADS + 1; k < TILE; ++k)
            cnt += sign_discord(a1, B[k]);
    } else {
        // Partial tile (generic, rare): guard everything.
        #pragma unroll
        for (int r = 0; r < 2; ++r) {
            const int i = i0 + r * NTHREADS;
            if (i < n) {
                const unsigned long long a = pack2(p[i], t[i]);
                for (int k = 0; k < jlim; ++k) {
                    if (jb + k > i) cnt += sign_discord(a, B[k]);
                }
            }
        }
    }

    // Block reduction: warp shuffle -> shared -> single atomic.
    #pragma unroll
    for (int off = 16; off > 0; off >>= 1)
        cnt += __shfl_down_sync(0xFFFFFFFFu, cnt, off);

    __shared__ unsigned int wsum[NTHREADS / 32];
    const int lane = tid & 31;
    const int wid = tid >> 5;
    if (lane == 0) wsum[wid] = cnt;
    __syncthreads();

    if (tid == 0) {
        unsigned int total = 0;
        #pragma unroll
        for (int w = 0; w < NTHREADS / 32; ++w) total += wsum[w];

        atomicAdd(&g_cnt, (unsigned long long)total);
        __threadfence();
        const unsigned int d = atomicAdd(&g_done, 1u);
        if (d == gridDim.x - 1) {
            // Last block: all g_cnt adds are visible (fence + done ordering).
            const unsigned long long D = atomicAdd(&g_cnt, 0ULL);
            const double nn = (double)n;
            out[0] = (float)(4.0 * (double)D / (nn * (nn - 1.0)));
            g_cnt = 0ULL;   // reset for next (graph-replayed) call
            g_done = 0u;
        }
    }
}

extern "C" void kernel_launch(void* const* d_in, const int* in_sizes, int n_in,
                              void* d_out, int out_size)
{
    const float* predictions = (const float*)d_in[0];
    const float* true_labels = (const float*)d_in[1];
    float* out = (float*)d_out;
    const int n = in_sizes[0];

    const int ntiles = (n + TILE - 1) / TILE;
    const int nblocks = ntiles * (ntiles + 1) / 2;

    kt_kernel<<<nblocks, NTHREADS>>>(predictions, true_labels, out, n);
}

// round 3
// speedup vs baseline: 1.3145x; 1.0270x over previous
#include <cuda_runtime.h>
#include <cstdint>

// Kendall's tau loss via discordant-pair count (no ties in random normals):
//   loss = 4*D / (n(n-1)),  D = #{i<j : sign(p_i-p_j) != sign(t_i-t_j)}
// Per pair: one packed f32x2 add computes both diffs; discord = XOR of the
// two halves' IEEE sign bits (LOP3 + LEA.HI in SASS).
// R3: TILE 512->256, 128-thread blocks, 2 rows/thread -> 528 blocks,
// ~14 warps/SM for latency hiding (R2 had 2 warps/SMSP, issue=49%).

#define TILE 256
#define NTHREADS 128

__device__ unsigned long long g_cnt = 0;
__device__ unsigned int g_done = 0;

__device__ __forceinline__ unsigned long long pack2(float lo, float hi) {
    unsigned long long r;
    asm("mov.b64 %0, {%1, %2};" : "=l"(r) : "f"(lo), "f"(hi));
    return r;
}

// a = (p_i, t_i), nb = (-p_j, -t_j). 1 if signs of the two diffs differ.
__device__ __forceinline__ unsigned int sign_discord(unsigned long long a,
                                                     unsigned long long nb) {
    unsigned long long s;
    asm("add.rn.f32x2 %0, %1, %2;" : "=l"(s) : "l"(a), "l"(nb));
    unsigned int lo, hi;
    asm("mov.b64 {%0, %1}, %2;" : "=r"(lo), "=r"(hi) : "l"(s));
    return (lo ^ hi) >> 31;
}

__global__ __launch_bounds__(NTHREADS) void kt_kernel(
    const float* __restrict__ p, const float* __restrict__ t,
    float* __restrict__ out, int n)
{
    const int ntiles = (n + TILE - 1) / TILE;

    // Decode linear block id -> upper-triangular (bi, bj), bj >= bi.
    int b = blockIdx.x;
    int bi = 0;
    while (b >= ntiles - bi) { b -= ntiles - bi; ++bi; }
    const int bj = bi + b;

    __shared__ float2 snb[TILE];  // (-p_j, -t_j) for this j-tile

    const int tid = threadIdx.x;
    const int jb = bj * TILE;
    const int jlim = min(TILE, n - jb);

    #pragma unroll
    for (int k = tid; k < TILE; k += NTHREADS) {
        if (k < jlim) snb[k] = make_float2(-p[jb + k], -t[jb + k]);
    }
    __syncthreads();

    const unsigned long long* B =
        reinterpret_cast<const unsigned long long*>(snb);

    const int i0 = bi * TILE + tid;
    const int i1 = i0 + NTHREADS;
    unsigned int cnt0 = 0, cnt1 = 0;

    const bool full = (jlim == TILE) && (bi * TILE + TILE <= n);

    if (full && bi != bj) {
        // Full off-diagonal tile: every (i, j) has i < j.
        const unsigned long long a0 = pack2(p[i0], t[i0]);
        const unsigned long long a1 = pack2(p[i1], t[i1]);
        #pragma unroll 8
        for (int k = 0; k < TILE; ++k) {
            const unsigned long long bk = B[k];
            cnt0 += sign_discord(a0, bk);
            cnt1 += sign_discord(a1, bk);
        }
    } else if (full) {
        // Full diagonal tile: j > i locally.
        const unsigned long long a0 = pack2(p[i0], t[i0]);
        const unsigned long long a1 = pack2(p[i1], t[i1]);
        #pragma unroll 8
        for (int k = tid + 1; k < TILE; ++k)
            cnt0 += sign_discord(a0, B[k]);
        #pragma unroll 8
        for (int k = tid + NTHREADS + 1; k < TILE; ++k)
            cnt1 += sign_discord(a1, B[k]);
    } else {
        // Partial tile (generic, rare): guard everything.
        #pragma unroll
        for (int r = 0; r < 2; ++r) {
            const int i = i0 + r * NTHREADS;
            if (i < n) {
                const unsigned long long a = pack2(p[i], t[i]);
                unsigned int c = 0;
                for (int k = 0; k < jlim; ++k)
                    if (jb + k > i) c += sign_discord(a, B[k]);
                if (r == 0) cnt0 += c; else cnt1 += c;
            }
        }
    }

    unsigned int cnt = cnt0 + cnt1;

    // Block reduction: warp shuffle -> shared -> single atomic.
    #pragma unroll
    for (int off = 16; off > 0; off >>= 1)
        cnt += __shfl_down_sync(0xFFFFFFFFu, cnt, off);

    __shared__ unsigned int wsum[NTHREADS / 32];
    const int lane = tid & 31;
    const int wid = tid >> 5;
    if (lane == 0) wsum[wid] = cnt;
    __syncthreads();

    if (tid == 0) {
        unsigned int total = 0;
        #pragma unroll
        for (int w = 0; w < NTHREADS / 32; ++w) total += wsum[w];

        atomicAdd(&g_cnt, (unsigned long long)total);
        __threadfence();
        const unsigned int d = atomicAdd(&g_done, 1u);
        if (d == gridDim.x - 1) {
            const unsigned long long D = atomicAdd(&g_cnt, 0ULL);
            const double nn = (double)n;
            out[0] = (float)(4.0 * (double)D / (nn * (nn - 1.0)));
            g_cnt = 0ULL;   // reset for next (graph-replayed) call
            g_done = 0u;
        }
    }
}

extern "C" void kernel_launch(void* const* d_in, const int* in_sizes, int n_in,
                              void* d_out, int out_size)
{
    const float* predictions = (const float*)d_in[0];
    const float* true_labels = (const float*)d_in[1];
    float* out = (float*)d_out;
    const int n = in_sizes[0];

    const int ntiles = (n + TILE - 1) / TILE;
    const int nblocks = ntiles * (ntiles + 1) / 2;

    kt_kernel<<<nblocks, NTHREADS>>>(predictions, true_labels, out, n);
}